// round 2
// baseline (speedup 1.0000x reference)
#include <cuda_runtime.h>
#include <math.h>

#define BB   2
#define NN   384
#define HIDD 128
#define NHH  8
#define ROWS (BB*NN)          // 768
#define RR   (BB*NN*NN)       // 294912
#define H_OUT_ELEMS (ROWS*HIDD)  // 98304

// ---------------- scratch (device globals; no allocation allowed) ----------
__device__ float g_h[ROWS*HIDD];
__device__ float g_Q[ROWS*HIDD];
__device__ float g_K[ROWS*HIDD];
__device__ float g_V[ROWS*HIDD];
__device__ float g_edge_attn[(size_t)RR*NHH];   // (b,i,j,h)
__device__ float g_attn_mean[RR];
__device__ float g_attn_out[ROWS*HIDD];
__device__ float g_hW[ROWS*HIDD];

// ---------------- helpers --------------------------------------------------
__device__ __forceinline__ float blockSum128(float v, float* red) {
    #pragma unroll
    for (int o = 16; o; o >>= 1) v += __shfl_xor_sync(0xffffffffu, v, o);
    int warp = threadIdx.x >> 5;
    if ((threadIdx.x & 31) == 0) red[warp] = v;
    __syncthreads();
    float s = red[0] + red[1] + red[2] + red[3];
    __syncthreads();
    return s;
}

// ---------------- K1: h = node@Wn+bn ; Q,K,V = h@W{q,k,v}+b ----------------
__global__ void k_node_qkv(const float* __restrict__ node,
                           const float* __restrict__ Wn, const float* __restrict__ bn,
                           const float* __restrict__ Wq, const float* __restrict__ bq,
                           const float* __restrict__ Wk, const float* __restrict__ bk,
                           const float* __restrict__ Wv, const float* __restrict__ bv) {
    int row = blockIdx.x;       // 0..767
    int c   = threadIdx.x;      // 0..127
    __shared__ float x[128];
    __shared__ float hh[128];
    x[c] = node[row*128 + c];
    __syncthreads();
    float acc = bn[c];
    #pragma unroll 4
    for (int k = 0; k < 128; k++) acc += x[k] * Wn[k*128 + c];
    g_h[row*128 + c] = acc;
    hh[c] = acc;
    __syncthreads();
    float aq = bq[c], ak = bk[c], av = bv[c];
    #pragma unroll 4
    for (int k = 0; k < 128; k++) {
        float hv = hh[k];
        aq += hv * Wq[k*128 + c];
        ak += hv * Wk[k*128 + c];
        av += hv * Wv[k*128 + c];
    }
    g_Q[row*128 + c] = aq;
    g_K[row*128 + c] = ak;
    g_V[row*128 + c] = av;
}

// ---------------- K2: big fused edge GEMM + gated head reduction -----------
// C = E(294912x128) @ [W_edge | W_gate](128x256); per row r, head h:
//   edge_attn[r][h] = sum_{d in head h} (C_edge + be) * sigmoid(C_gate + bg)
#define BM 64
#define BK 32
#define LDA 68
__global__ __launch_bounds__(256, 2)
void k_edge_gemm(const float* __restrict__ E,
                 const float* __restrict__ We, const float* __restrict__ be,
                 const float* __restrict__ Wg, const float* __restrict__ bg) {
    __shared__ float As[BK][LDA];     // k-major, m contiguous (padded)
    __shared__ float Bs[BK][256];
    int row0 = blockIdx.x * BM;
    int tid  = threadIdx.x;
    int tm   = tid >> 5;              // 0..7 (== warp id)
    int tn   = tid & 31;              // 0..31 (== lane)

    float acc[8][8];
    #pragma unroll
    for (int i = 0; i < 8; i++)
        #pragma unroll
        for (int j = 0; j < 8; j++) acc[i][j] = 0.f;

    for (int ck = 0; ck < 4; ck++) {
        int k0 = ck * BK;
        // --- load A tile (64 rows x 32 k) coalesced, store transposed -----
        for (int idx = tid; idx < 64*8; idx += 256) {
            int kq = idx & 7;          // 0..7 -> 4 k's each
            int m  = idx >> 3;         // 0..63
            float4 v = *(const float4*)&E[(size_t)(row0 + m)*128 + k0 + kq*4];
            As[kq*4+0][m] = v.x; As[kq*4+1][m] = v.y;
            As[kq*4+2][m] = v.z; As[kq*4+3][m] = v.w;
        }
        // --- load B tile (32 k x 256 cols = [We|Wg]) ----------------------
        for (int idx = tid; idx < 32*64; idx += 256) {
            int kk = idx >> 6;
            int nq = idx & 63;
            const float* src = (nq < 32) ? &We[(k0+kk)*128 + nq*4]
                                         : &Wg[(k0+kk)*128 + (nq-32)*4];
            *(float4*)&Bs[kk][nq*4] = *(const float4*)src;
        }
        __syncthreads();
        #pragma unroll 4
        for (int kk = 0; kk < BK; kk++) {
            float a[8], b[8];
            *(float4*)&a[0] = *(const float4*)&As[kk][tm*8];
            *(float4*)&a[4] = *(const float4*)&As[kk][tm*8 + 4];
            *(float4*)&b[0] = *(const float4*)&Bs[kk][tn*8];
            *(float4*)&b[4] = *(const float4*)&Bs[kk][tn*8 + 4];
            #pragma unroll
            for (int i = 0; i < 8; i++)
                #pragma unroll
                for (int j = 0; j < 8; j++) acc[i][j] += a[i] * b[j];
        }
        __syncthreads();
    }

    // biases (col-dependent): lanes 0..15 hold edge cols, 16..31 gate cols
    {
        const float* bptr = (tn < 16) ? &be[tn*8] : &bg[(tn-16)*8];
        float bias[8];
        #pragma unroll
        for (int j = 0; j < 8; j++) bias[j] = bptr[j];
        #pragma unroll
        for (int i = 0; i < 8; i++)
            #pragma unroll
            for (int j = 0; j < 8; j++) acc[i][j] += bias[j];
    }

    // epilogue: pair edge lane l with gate lane l+16 via shfl, gated sum,
    // then combine lane pairs (2h,2h+1) -> one head value per even lane.
    #pragma unroll
    for (int i = 0; i < 8; i++) {
        float part = 0.f;
        #pragma unroll
        for (int j = 0; j < 8; j++) {
            float other = __shfl_xor_sync(0xffffffffu, acc[i][j], 16);
            float gate  = 1.f / (1.f + __expf(-other));
            part += acc[i][j] * gate;       // meaningful only for lanes < 16
        }
        float o2 = __shfl_xor_sync(0xffffffffu, part, 1);
        float att = part + o2;
        if (tn < 16 && (tn & 1) == 0) {
            int h = tn >> 1;
            g_edge_attn[(size_t)(row0 + tm*8 + i)*8 + h] = att;
        }
    }
}

// ---------------- K3: attention (per (b,i)): scores+bias+mask+softmax ------
//                       + attn_mean + attn_out
__global__ void k_attn(const int* __restrict__ adj) {
    int bi = blockIdx.x;            // 0..767
    int b  = bi / NN, i = bi % NN;
    int t  = threadIdx.x;           // 0..383
    __shared__ float q[128];
    __shared__ float p[NHH * NN];   // 12 KB
    __shared__ float rsum[NHH];

    if (t < 128) q[t] = g_Q[bi*128 + t];
    __syncthreads();

    // scores for column j = t, all 8 heads
    {
        int j = t;
        float acc[8];
        #pragma unroll
        for (int h = 0; h < 8; h++) acc[h] = 0.f;
        const float4* kr = (const float4*)&g_K[(size_t)(b*NN + j)*128];
        #pragma unroll
        for (int w = 0; w < 32; w++) {
            float4 kv = kr[w];
            const float* qq = &q[w*4];
            acc[w >> 2] += kv.x*qq[0] + kv.y*qq[1] + kv.z*qq[2] + kv.w*qq[3];
        }
        int msk = adj[(size_t)(b*NN + i)*NN + j];
        const float* ea = &g_edge_attn[((size_t)(b*NN + i)*NN + j)*8];
        #pragma unroll
        for (int h = 0; h < 8; h++) {
            float s = acc[h] * 0.25f + ea[h];
            p[h*NN + j] = (msk == 0) ? -1e9f : s;
        }
    }
    __syncthreads();

    // per-head softmax: warp h handles head h
    int warp = t >> 5, lane = t & 31;
    if (warp < 8) {
        float mx = -INFINITY;
        for (int j = lane; j < NN; j += 32) mx = fmaxf(mx, p[warp*NN + j]);
        #pragma unroll
        for (int o = 16; o; o >>= 1) mx = fmaxf(mx, __shfl_xor_sync(0xffffffffu, mx, o));
        float sum = 0.f;
        for (int j = lane; j < NN; j += 32) {
            float e = __expf(p[warp*NN + j] - mx);
            p[warp*NN + j] = e;
            sum += e;
        }
        #pragma unroll
        for (int o = 16; o; o >>= 1) sum += __shfl_xor_sync(0xffffffffu, sum, o);
        if (lane == 0) rsum[warp] = 1.f / sum;
    }
    __syncthreads();

    // normalize + attn_mean
    {
        int j = t;
        float am = 0.f;
        #pragma unroll
        for (int h = 0; h < 8; h++) {
            float v = p[h*NN + j] * rsum[h];
            p[h*NN + j] = v;
            am += v;
        }
        g_attn_mean[(size_t)(b*NN + i)*NN + j] = am * 0.125f;
    }
    __syncthreads();

    // attn_out: threads 0..127 = (h*16+d)
    if (t < 128) {
        int h = t >> 4;
        float a0 = 0.f, a1 = 0.f, a2 = 0.f, a3 = 0.f;
        const float* pv = &p[h*NN];
        #pragma unroll 4
        for (int j = 0; j < NN; j += 4) {
            a0 += pv[j+0] * g_V[(size_t)(b*NN + j+0)*128 + t];
            a1 += pv[j+1] * g_V[(size_t)(b*NN + j+1)*128 + t];
            a2 += pv[j+2] * g_V[(size_t)(b*NN + j+2)*128 + t];
            a3 += pv[j+3] * g_V[(size_t)(b*NN + j+3)*128 + t];
        }
        g_attn_out[bi*128 + t] = (a0 + a1) + (a2 + a3);
    }
}

// ---------------- K4: h_final = LN(residual + attn_out@Wo + bo) ------------
__global__ void k_hfinal(const float* __restrict__ Wo, const float* __restrict__ bo,
                         const float* __restrict__ g1, const float* __restrict__ be1,
                         float* __restrict__ out) {
    int row = blockIdx.x;
    int c   = threadIdx.x;
    __shared__ float a[128];
    __shared__ float red[4];
    a[c] = g_attn_out[row*128 + c];
    __syncthreads();
    float acc = bo[c] + g_h[row*128 + c];
    #pragma unroll 4
    for (int k = 0; k < 128; k++) acc += a[k] * Wo[k*128 + c];
    float m = blockSum128(acc, red) * (1.f/128.f);
    float d = acc - m;
    float var = blockSum128(d*d, red) * (1.f/128.f);
    out[row*128 + c] = d * rsqrtf(var + 1e-5f) * g1[c] + be1[c];
}

// ---------------- K5: hW = h_final @ W_eout --------------------------------
__global__ void k_hW(const float* __restrict__ hf, const float* __restrict__ Weo) {
    int row = blockIdx.x;
    int c   = threadIdx.x;
    __shared__ float a[128];
    a[c] = hf[row*128 + c];
    __syncthreads();
    float acc = 0.f;
    #pragma unroll 4
    for (int k = 0; k < 128; k++) acc += a[k] * Weo[k*128 + c];
    g_hW[row*128 + c] = acc;
}

// ---------------- K6: edge_out = LN(E + attn_mean*0.5*(hW_i+hW_j) + beo) ---
__global__ void k_edge_out(const float* __restrict__ E, const float* __restrict__ beo,
                           const float* __restrict__ g2, const float* __restrict__ be2,
                           float* __restrict__ out) {
    int row = blockIdx.x;           // 0..294911
    int c   = threadIdx.x;          // 0..127
    int b   = row / (NN*NN);
    int rem = row - b*NN*NN;
    int i   = rem / NN;
    int j   = rem - i*NN;
    float am = 0.5f * g_attn_mean[row];
    float v = E[(size_t)row*128 + c]
            + am * (g_hW[(b*NN + i)*128 + c] + g_hW[(b*NN + j)*128 + c])
            + beo[c];
    __shared__ float red[4];
    float m = blockSum128(v, red) * (1.f/128.f);
    float d = v - m;
    float var = blockSum128(d*d, red) * (1.f/128.f);
    out[(size_t)H_OUT_ELEMS + (size_t)row*128 + c] =
        d * rsqrtf(var + 1e-5f) * g2[c] + be2[c];
}

// ---------------- launch ---------------------------------------------------
extern "C" void kernel_launch(void* const* d_in, const int* in_sizes, int n_in,
                              void* d_out, int out_size) {
    const float* node = (const float*)d_in[0];
    const float* edge = (const float*)d_in[1];
    const int*   adj  = (const int*)  d_in[2];
    const float* Wn  = (const float*)d_in[3];  const float* bn  = (const float*)d_in[4];
    const float* Wq  = (const float*)d_in[5];  const float* bq  = (const float*)d_in[6];
    const float* Wk  = (const float*)d_in[7];  const float* bk  = (const float*)d_in[8];
    const float* Wv  = (const float*)d_in[9];  const float* bv  = (const float*)d_in[10];
    const float* We  = (const float*)d_in[11]; const float* be  = (const float*)d_in[12];
    const float* Wg  = (const float*)d_in[13]; const float* bg  = (const float*)d_in[14];
    const float* Wo  = (const float*)d_in[15]; const float* bo  = (const float*)d_in[16];
    const float* Weo = (const float*)d_in[17]; const float* beo = (const float*)d_in[18];
    const float* g1  = (const float*)d_in[19]; const float* be1 = (const float*)d_in[20];
    const float* g2  = (const float*)d_in[21]; const float* be2 = (const float*)d_in[22];
    float* out = (float*)d_out;

    k_node_qkv<<<ROWS, 128>>>(node, Wn, bn, Wq, bq, Wk, bk, Wv, bv);
    k_edge_gemm<<<RR / BM, 256>>>(edge, We, be, Wg, bg);
    k_attn<<<ROWS, 384>>>(adj);
    k_hfinal<<<ROWS, 128>>>(Wo, bo, g1, be1, out);
    k_hW<<<ROWS, 128>>>(out, Weo);
    k_edge_out<<<RR, 128>>>(edge, beo, g2, be2, out);
}

// round 4
// speedup vs baseline: 2.3060x; 2.3060x over previous
#include <cuda_runtime.h>
#include <math.h>
#include <stdint.h>

#define BB   2
#define NN   384
#define HIDD 128
#define NHH  8
#define ROWS (BB*NN)          // 768
#define RR   (BB*NN*NN)       // 294912
#define H_OUT_ELEMS (ROWS*HIDD)  // 98304

// ---------------- scratch (device globals; no allocation allowed) ----------
__device__ float g_h[ROWS*HIDD];
__device__ float g_Q[ROWS*HIDD];
__device__ float g_K[ROWS*HIDD];
__device__ float g_V[ROWS*HIDD];
__device__ float g_edge_attn[(size_t)RR*NHH];   // (b,i,j,h)
__device__ float g_attn_mean[RR];
__device__ float g_attn_out[ROWS*HIDD];
__device__ float g_hW[ROWS*HIDD];

// ---------------- helpers --------------------------------------------------
__device__ __forceinline__ uint32_t f2tf32(float f) {
    uint32_t r;
    asm("cvt.rna.tf32.f32 %0, %1;" : "=r"(r) : "f"(f));
    return r;
}

__device__ __forceinline__ void mma_tf32(float* d, const uint32_t* a, const uint32_t* b) {
    asm volatile(
        "mma.sync.aligned.m16n8k8.row.col.f32.tf32.tf32.f32 "
        "{%0,%1,%2,%3}, {%4,%5,%6,%7}, {%8,%9}, {%0,%1,%2,%3};"
        : "+f"(d[0]), "+f"(d[1]), "+f"(d[2]), "+f"(d[3])
        : "r"(a[0]), "r"(a[1]), "r"(a[2]), "r"(a[3]), "r"(b[0]), "r"(b[1]));
}

__device__ __forceinline__ float blockSum128(float v, float* red) {
    #pragma unroll
    for (int o = 16; o; o >>= 1) v += __shfl_xor_sync(0xffffffffu, v, o);
    int warp = threadIdx.x >> 5;
    if ((threadIdx.x & 31) == 0) red[warp] = v;
    __syncthreads();
    float s = red[0] + red[1] + red[2] + red[3];
    __syncthreads();
    return s;
}

// ---------------- K1: h = node@Wn+bn ; Q,K,V = h@W{q,k,v}+b ----------------
__global__ void k_node_qkv(const float* __restrict__ node,
                           const float* __restrict__ Wn, const float* __restrict__ bn,
                           const float* __restrict__ Wq, const float* __restrict__ bq,
                           const float* __restrict__ Wk, const float* __restrict__ bk,
                           const float* __restrict__ Wv, const float* __restrict__ bv) {
    int row = blockIdx.x;
    int c   = threadIdx.x;
    __shared__ float x[128];
    __shared__ float hh[128];
    x[c] = node[row*128 + c];
    __syncthreads();
    float acc = bn[c];
    #pragma unroll 4
    for (int k = 0; k < 128; k++) acc += x[k] * Wn[k*128 + c];
    g_h[row*128 + c] = acc;
    hh[c] = acc;
    __syncthreads();
    float aq = bq[c], ak = bk[c], av = bv[c];
    #pragma unroll 4
    for (int k = 0; k < 128; k++) {
        float hv = hh[k];
        aq += hv * Wq[k*128 + c];
        ak += hv * Wk[k*128 + c];
        av += hv * Wv[k*128 + c];
    }
    g_Q[row*128 + c] = aq;
    g_K[row*128 + c] = ak;
    g_V[row*128 + c] = av;
}

// ---------------- K2: mma.sync tf32 edge GEMM + gated head reduction -------
// C[294912 x 256] = E @ [W_edge | W_gate]; per row r, head h:
//   edge_attn[r][h] = sum_{d in head h} (C_e + be[d]) * sigmoid(C_g + bg[d])
#define TILES_TOTAL   (RR/128)     // 2304
#define GRID_K2       144
#define TILES_PER_CTA (TILES_TOTAL/GRID_K2)  // 16

#define ALD 132                    // A smem stride (floats): %32 == 4
#define BLD 264                    // B smem stride (floats): %32 == 8
#define SM_AS   0                  // 128*132*4 = 67584 B
#define SM_BS   67584              // 128*264*4 = 135168 B
#define SM_BE   (SM_BS + 135168)   // 512 B
#define SM_BG   (SM_BE + 512)
#define SM_K2_TOTAL (SM_BG + 512)  // 204800 B

__global__ __launch_bounds__(512, 1)
void k_edge_gemm_mma(const float* __restrict__ E,
                     const float* __restrict__ We, const float* __restrict__ be,
                     const float* __restrict__ Wg, const float* __restrict__ bg) {
    extern __shared__ char smem[];
    uint32_t* As = (uint32_t*)(smem + SM_AS);
    uint32_t* Bs = (uint32_t*)(smem + SM_BS);
    float* sm_be = (float*)(smem + SM_BE);
    float* sm_bg = (float*)(smem + SM_BG);

    int tid  = threadIdx.x;
    int wid  = tid >> 5;
    int lane = tid & 31;
    int gid  = lane >> 2;      // 0..7
    int tig  = lane & 3;       // 0..3
    int wm   = wid >> 2;       // 0..3  (32-row group)
    int wn   = wid & 3;        // 0..3  (32-col group; +gate pair at +128)

    if (tid < 128) { sm_be[tid] = be[tid]; sm_bg[tid] = bg[tid]; }

    // ---- load B = [We | Wg] once: Bs[k][n], n<128 edge, n>=128 gate -------
    for (int idx = tid; idx < 128*64; idx += 512) {
        int k  = idx >> 6;
        int f4 = idx & 63;
        int n0 = f4 * 4;
        const float4 v = (n0 < 128)
            ? *(const float4*)&We[k*128 + n0]
            : *(const float4*)&Wg[k*128 + (n0 - 128)];
        uint32_t* dst = &Bs[k*BLD + n0];
        dst[0] = f2tf32(v.x); dst[1] = f2tf32(v.y);
        dst[2] = f2tf32(v.z); dst[3] = f2tf32(v.w);
    }

    int r0  = wm * 32;
    int nc0 = wn * 32;

    for (int it = 0; it < TILES_PER_CTA; it++) {
        size_t row0 = (size_t)(blockIdx.x * TILES_PER_CTA + it) * 128;

        __syncthreads();   // prior iter's LDS done (and first-iter B ordering)
        // ---- load A tile 128x128 into As (tf32) ---------------------------
        const float4* Erow = (const float4*)(E + row0*128);
        #pragma unroll
        for (int i = 0; i < 8; i++) {
            int idx = tid + i*512;
            int m   = idx >> 5;
            int f4  = idx & 31;
            float4 v = Erow[(size_t)m*32 + f4];
            uint32_t* dst = &As[m*ALD + f4*4];
            dst[0] = f2tf32(v.x); dst[1] = f2tf32(v.y);
            dst[2] = f2tf32(v.z); dst[3] = f2tf32(v.w);
        }
        __syncthreads();

        // ---- 128x(32e+32g)x128 per warp via m16n8k8 -----------------------
        float accE[2][4][4], accG[2][4][4];
        #pragma unroll
        for (int mf = 0; mf < 2; mf++)
            #pragma unroll
            for (int nf = 0; nf < 4; nf++)
                #pragma unroll
                for (int q = 0; q < 4; q++) { accE[mf][nf][q] = 0.f; accG[mf][nf][q] = 0.f; }

        #pragma unroll
        for (int ks = 0; ks < 16; ks++) {
            int k0 = ks * 8;
            uint32_t aF[2][4];
            #pragma unroll
            for (int mf = 0; mf < 2; mf++) {
                int rr = r0 + mf*16;
                aF[mf][0] = As[(rr + gid    )*ALD + k0 + tig    ];
                aF[mf][1] = As[(rr + 8 + gid)*ALD + k0 + tig    ];
                aF[mf][2] = As[(rr + gid    )*ALD + k0 + tig + 4];
                aF[mf][3] = As[(rr + 8 + gid)*ALD + k0 + tig + 4];
            }
            uint32_t bE[4][2], bG[4][2];
            #pragma unroll
            for (int nf = 0; nf < 4; nf++) {
                int n = nc0 + nf*8 + gid;
                bE[nf][0] = Bs[(k0 + tig    )*BLD + n];
                bE[nf][1] = Bs[(k0 + tig + 4)*BLD + n];
                bG[nf][0] = Bs[(k0 + tig    )*BLD + 128 + n];
                bG[nf][1] = Bs[(k0 + tig + 4)*BLD + 128 + n];
            }
            #pragma unroll
            for (int mf = 0; mf < 2; mf++)
                #pragma unroll
                for (int nf = 0; nf < 4; nf++) {
                    mma_tf32(accE[mf][nf], aF[mf], bE[nf]);
                    mma_tf32(accG[mf][nf], aF[mf], bG[nf]);
                }
        }

        // ---- epilogue: bias + sigmoid gate + head-16 sums -----------------
        // thread accum (mf, nf, q): row = r0+mf*16 + (q>=2 ? 8:0) + gid,
        //                           col = nc0 + nf*8 + 2*tig + (q&1)
        float hs[2][2][2];   // [mf][rowHalf][headLocal]
        #pragma unroll
        for (int a = 0; a < 2; a++)
            #pragma unroll
            for (int b2 = 0; b2 < 2; b2++) { hs[a][b2][0] = 0.f; hs[a][b2][1] = 0.f; }

        #pragma unroll
        for (int mf = 0; mf < 2; mf++)
            #pragma unroll
            for (int nf = 0; nf < 4; nf++) {
                int col0 = nc0 + nf*8 + 2*tig;
                int hl   = nf >> 1;
                float be0 = sm_be[col0], be1 = sm_be[col0+1];
                float bg0 = sm_bg[col0], bg1 = sm_bg[col0+1];
                float v00 = (accE[mf][nf][0] + be0) * (1.f/(1.f + __expf(-(accG[mf][nf][0] + bg0))));
                float v01 = (accE[mf][nf][1] + be1) * (1.f/(1.f + __expf(-(accG[mf][nf][1] + bg1))));
                float v10 = (accE[mf][nf][2] + be0) * (1.f/(1.f + __expf(-(accG[mf][nf][2] + bg0))));
                float v11 = (accE[mf][nf][3] + be1) * (1.f/(1.f + __expf(-(accG[mf][nf][3] + bg1))));
                hs[mf][0][hl] += v00 + v01;
                hs[mf][1][hl] += v10 + v11;
            }

        // reduce across the 4 lanes of each group (tig bits = lane bits 0,1)
        #pragma unroll
        for (int mf = 0; mf < 2; mf++)
            #pragma unroll
            for (int rh = 0; rh < 2; rh++)
                #pragma unroll
                for (int hl = 0; hl < 2; hl++) {
                    float v = hs[mf][rh][hl];
                    v += __shfl_xor_sync(0xffffffffu, v, 1);
                    v += __shfl_xor_sync(0xffffffffu, v, 2);
                    hs[mf][rh][hl] = v;
                }

        if (tig == 0) {
            #pragma unroll
            for (int mf = 0; mf < 2; mf++)
                #pragma unroll
                for (int rh = 0; rh < 2; rh++) {
                    size_t grow = row0 + r0 + mf*16 + rh*8 + gid;
                    int h0 = wn*2;
                    g_edge_attn[grow*8 + h0    ] = hs[mf][rh][0];
                    g_edge_attn[grow*8 + h0 + 1] = hs[mf][rh][1];
                }
        }
    }
}

// ---------------- K3: attention (per (b,i)) --------------------------------
__global__ void k_attn(const int* __restrict__ adj) {
    int bi = blockIdx.x;
    int b  = bi / NN, i = bi % NN;
    int t  = threadIdx.x;           // 0..383
    __shared__ float q[128];
    __shared__ float p[NHH * NN];
    __shared__ float rsum[NHH];

    if (t < 128) q[t] = g_Q[bi*128 + t];
    __syncthreads();

    {
        int j = t;
        float acc[8];
        #pragma unroll
        for (int h = 0; h < 8; h++) acc[h] = 0.f;
        const float4* kr = (const float4*)&g_K[(size_t)(b*NN + j)*128];
        #pragma unroll
        for (int w = 0; w < 32; w++) {
            float4 kv = kr[w];
            const float* qq = &q[w*4];
            acc[w >> 2] += kv.x*qq[0] + kv.y*qq[1] + kv.z*qq[2] + kv.w*qq[3];
        }
        int msk = adj[(size_t)(b*NN + i)*NN + j];
        const float* ea = &g_edge_attn[((size_t)(b*NN + i)*NN + j)*8];
        #pragma unroll
        for (int h = 0; h < 8; h++) {
            float s = acc[h] * 0.25f + ea[h];
            p[h*NN + j] = (msk == 0) ? -1e9f : s;
        }
    }
    __syncthreads();

    int warp = t >> 5, lane = t & 31;
    if (warp < 8) {
        float mx = -INFINITY;
        for (int j = lane; j < NN; j += 32) mx = fmaxf(mx, p[warp*NN + j]);
        #pragma unroll
        for (int o = 16; o; o >>= 1) mx = fmaxf(mx, __shfl_xor_sync(0xffffffffu, mx, o));
        float sum = 0.f;
        for (int j = lane; j < NN; j += 32) {
            float e = __expf(p[warp*NN + j] - mx);
            p[warp*NN + j] = e;
            sum += e;
        }
        #pragma unroll
        for (int o = 16; o; o >>= 1) sum += __shfl_xor_sync(0xffffffffu, sum, o);
        if (lane == 0) rsum[warp] = 1.f / sum;
    }
    __syncthreads();

    {
        int j = t;
        float am = 0.f;
        #pragma unroll
        for (int h = 0; h < 8; h++) {
            float v = p[h*NN + j] * rsum[h];
            p[h*NN + j] = v;
            am += v;
        }
        g_attn_mean[(size_t)(b*NN + i)*NN + j] = am * 0.125f;
    }
    __syncthreads();

    if (t < 128) {
        int h = t >> 4;
        float a0 = 0.f, a1 = 0.f, a2 = 0.f, a3 = 0.f;
        const float* pv = &p[h*NN];
        #pragma unroll 4
        for (int j = 0; j < NN; j += 4) {
            a0 += pv[j+0] * g_V[(size_t)(b*NN + j+0)*128 + t];
            a1 += pv[j+1] * g_V[(size_t)(b*NN + j+1)*128 + t];
            a2 += pv[j+2] * g_V[(size_t)(b*NN + j+2)*128 + t];
            a3 += pv[j+3] * g_V[(size_t)(b*NN + j+3)*128 + t];
        }
        g_attn_out[bi*128 + t] = (a0 + a1) + (a2 + a3);
    }
}

// ---------------- K4: h_final = LN(residual + attn_out@Wo + bo); hW --------
__global__ void k_hfinal(const float* __restrict__ Wo, const float* __restrict__ bo,
                         const float* __restrict__ g1, const float* __restrict__ be1,
                         const float* __restrict__ Weo,
                         float* __restrict__ out) {
    int row = blockIdx.x;
    int c   = threadIdx.x;
    __shared__ float a[128];
    __shared__ float hf[128];
    __shared__ float red[4];
    a[c] = g_attn_out[row*128 + c];
    __syncthreads();
    float acc = bo[c] + g_h[row*128 + c];
    #pragma unroll 4
    for (int k = 0; k < 128; k++) acc += a[k] * Wo[k*128 + c];
    float m = blockSum128(acc, red) * (1.f/128.f);
    float d = acc - m;
    float var = blockSum128(d*d, red) * (1.f/128.f);
    float hv = d * rsqrtf(var + 1e-5f) * g1[c] + be1[c];
    out[row*128 + c] = hv;
    hf[c] = hv;
    __syncthreads();
    float acc2 = 0.f;
    #pragma unroll 4
    for (int k = 0; k < 128; k++) acc2 += hf[k] * Weo[k*128 + c];
    g_hW[row*128 + c] = acc2;
}

// ---------------- K6: edge_out = LN(E + attn_mean*0.5*(hW_i+hW_j) + beo) ---
// warp-per-row, float4 lanes, shfl-only reductions
__global__ __launch_bounds__(256)
void k_edge_out(const float* __restrict__ E, const float* __restrict__ beo,
                const float* __restrict__ g2, const float* __restrict__ be2,
                float* __restrict__ out) {
    int warp = threadIdx.x >> 5;
    int lane = threadIdx.x & 31;
    size_t row = (size_t)blockIdx.x * 8 + warp;     // 0..RR-1
    int b   = (int)(row / (NN*NN));
    int rem = (int)(row - (size_t)b*NN*NN);
    int i   = rem / NN;
    int j   = rem - i*NN;

    float am = 0.5f * g_attn_mean[row];
    float4 e  = ((const float4*)E)[row*32 + lane];
    float4 hi = ((const float4*)g_hW)[(size_t)(b*NN + i)*32 + lane];
    float4 hj = ((const float4*)g_hW)[(size_t)(b*NN + j)*32 + lane];
    float4 bo4 = ((const float4*)beo)[lane];

    float vx = e.x + am*(hi.x + hj.x) + bo4.x;
    float vy = e.y + am*(hi.y + hj.y) + bo4.y;
    float vz = e.z + am*(hi.z + hj.z) + bo4.z;
    float vw = e.w + am*(hi.w + hj.w) + bo4.w;

    float s = vx + vy + vz + vw;
    #pragma unroll
    for (int o = 16; o; o >>= 1) s += __shfl_xor_sync(0xffffffffu, s, o);
    float m = s * (1.f/128.f);

    float dx = vx - m, dy = vy - m, dz = vz - m, dw = vw - m;
    float q = dx*dx + dy*dy + dz*dz + dw*dw;
    #pragma unroll
    for (int o = 16; o; o >>= 1) q += __shfl_xor_sync(0xffffffffu, q, o);
    float rstd = rsqrtf(q * (1.f/128.f) + 1e-5f);

    float4 gg = ((const float4*)g2)[lane];
    float4 bb = ((const float4*)be2)[lane];
    float4 o4;
    o4.x = dx * rstd * gg.x + bb.x;
    o4.y = dy * rstd * gg.y + bb.y;
    o4.z = dz * rstd * gg.z + bb.z;
    o4.w = dw * rstd * gg.w + bb.w;
    ((float4*)(out + H_OUT_ELEMS))[row*32 + lane] = o4;
}

// ---------------- launch ---------------------------------------------------
extern "C" void kernel_launch(void* const* d_in, const int* in_sizes, int n_in,
                              void* d_out, int out_size) {
    const float* node = (const float*)d_in[0];
    const float* edge = (const float*)d_in[1];
    const int*   adj  = (const int*)  d_in[2];
    const float* Wn  = (const float*)d_in[3];  const float* bn  = (const float*)d_in[4];
    const float* Wq  = (const float*)d_in[5];  const float* bq  = (const float*)d_in[6];
    const float* Wk  = (const float*)d_in[7];  const float* bk  = (const float*)d_in[8];
    const float* Wv  = (const float*)d_in[9];  const float* bv  = (const float*)d_in[10];
    const float* We  = (const float*)d_in[11]; const float* be  = (const float*)d_in[12];
    const float* Wg  = (const float*)d_in[13]; const float* bg  = (const float*)d_in[14];
    const float* Wo  = (const float*)d_in[15]; const float* bo  = (const float*)d_in[16];
    const float* Weo = (const float*)d_in[17]; const float* beo = (const float*)d_in[18];
    const float* g1  = (const float*)d_in[19]; const float* be1 = (const float*)d_in[20];
    const float* g2  = (const float*)d_in[21]; const float* be2 = (const float*)d_in[22];
    float* out = (float*)d_out;

    cudaFuncSetAttribute(k_edge_gemm_mma,
                         cudaFuncAttributeMaxDynamicSharedMemorySize, SM_K2_TOTAL);

    k_node_qkv<<<ROWS, 128>>>(node, Wn, bn, Wq, bq, Wk, bk, Wv, bv);
    k_edge_gemm_mma<<<GRID_K2, 512, SM_K2_TOTAL>>>(edge, We, be, Wg, bg);
    k_attn<<<ROWS, 384>>>(adj);
    k_hfinal<<<ROWS, 128>>>(Wo, bo, g1, be1, Weo, out);
    k_edge_out<<<RR/8, 256>>>(edge, beo, g2, be2, out);
}